// round 12
// baseline (speedup 1.0000x reference)
#include <cuda_runtime.h>
#include <cstdint>

typedef unsigned int u32;
typedef unsigned short u16;

#define KCODES 1024
#define DIM 64
#define NROWS 65536
#define THREADS 512
#define RPC 512          // rows per CTA
#define NT 128           // n-tiles of 8 codes
#define NIT (NT / 2)     // GEMM iterations (2 tiles each)
#define CAP 24           // candidate cap per row (overflow -> exact full scan)
#define NCTA 128

// Scratch (no device allocation allowed -> __device__ globals)
__device__ int    g_counts[KCODES];
__device__ float  g_Esq[KCODES];
__device__ double g_loss;
__device__ int    g_done;
__device__ __align__(16) u32 g_Ebf[KCODES * 32];  // bf16x2-packed codebook

// ---------------------------------------------------------------------------
// SMEM layout (bytes). E rows 36 u32 (144B) in PERMUTED frag order:
//   sE[code*36 + (j&3)*8 + q] holds original k-pair u32 j = 4q + (j&3),
// so one lane's 8 B-frag words for a tile are 8 contiguous u32 -> 2x LDS.128.
// ---------------------------------------------------------------------------
#define SE_OFF    0          // E bf16 [1024][36 u32]            147456
#define SQ_OFF    147456     // esq f32 [1024]                     4096
#define SCAND_OFF 151552     // cand u16 [512][CAP]               24576
#define SCNT_OFF  176128     // counts int [512]                   2048
#define SMX_OFF   178176     // misc f32 [16] (emax / loss)          64
#define SMEM_SZ   178240

// ---------------------------------------------------------------------------
// Kernel 1: esq (exact fp32 sequential chain - DO NOT reorder, bit-feeds the
// verified d chain) + bf16x2-pack E + zero accumulators. 32x32 for latency.
// ---------------------------------------------------------------------------
__global__ void prep_kernel(const float* __restrict__ E) {
    int k = blockIdx.x * 32 + threadIdx.x;
    if (k < KCODES) {
        float e[64];
        const float4* er = (const float4*)(E + k * DIM);
        #pragma unroll
        for (int i = 0; i < 16; i++) {
            float4 v = er[i];
            e[4*i] = v.x; e[4*i+1] = v.y; e[4*i+2] = v.z; e[4*i+3] = v.w;
        }
        float s = 0.f;
        #pragma unroll
        for (int d = 0; d < 64; d++) s = fmaf(e[d], e[d], s);
        g_Esq[k] = s;
        g_counts[k] = 0;
        #pragma unroll
        for (int i = 0; i < 32; i++) {
            u32 pr;  // lo = dim 2i, hi = dim 2i+1
            asm("cvt.rn.bf16x2.f32 %0, %1, %2;" : "=r"(pr) : "f"(e[2*i+1]), "f"(e[2*i]));
            g_Ebf[k * 32 + i] = pr;
        }
    }
    if (k == 0) { g_loss = 0.0; g_done = 0; }
}

// ---------------------------------------------------------------------------
// m16n8k16 bf16 mma, fp32 accumulate (base PTX, works on plain sm_103)
// ---------------------------------------------------------------------------
__device__ __forceinline__ void mma16816(float d[4], const u32 a[4], const u32 b[2]) {
    asm("mma.sync.aligned.m16n8k16.row.col.f32.bf16.bf16.f32 "
        "{%0,%1,%2,%3}, {%4,%5,%6,%7}, {%8,%9}, {%0,%1,%2,%3};"
        : "+f"(d[0]), "+f"(d[1]), "+f"(d[2]), "+f"(d[3])
        : "r"(a[0]), "r"(a[1]), "r"(a[2]), "r"(a[3]), "r"(b[0]), "r"(b[1]));
}

// ---------------------------------------------------------------------------
// Kernel 2: SINGLE-pass bf16 HMMA min+collect (stale quad-synced threshold is
// conservative: it only over-collects, never misses the winner), iteration 0
// collect-disabled and revisited at the end vs the final threshold.
// -> exact refine -> fused gather/loss -> last-CTA finalize.
// Exact path = the R2-verified bit chain.
// ---------------------------------------------------------------------------
__global__ void __launch_bounds__(THREADS, 1)
vq_main(const float* __restrict__ in, const float* __restrict__ E,
        float* __restrict__ out) {
    extern __shared__ __align__(16) char S[];
    u32*   sE    = (u32*)(S + SE_OFF);
    float* sq    = (float*)(S + SQ_OFF);
    u16*   scand = (u16*)(S + SCAND_OFF);
    int*   scnt  = (int*)(S + SCNT_OFF);
    float* smx   = (float*)(S + SMX_OFF);
    __shared__ int s_islast;

    const int t = threadIdx.x;
    const int w = t >> 5, l = t & 31;
    const int n = blockIdx.x * RPC + t;
    const int b = n >> 10, p = n & 1023;

    // --- stage E permuted: sE[code*36 + c*8 + q] = component c of uint4 q ---
    {
        const uint4* esrc = (const uint4*)g_Ebf;
        #pragma unroll
        for (int i = 0; i < 16; i++) {
            int lin = t + i * 512;              // uint4 index
            int code = lin >> 3, q = lin & 7;
            uint4 v = esrc[lin];
            u32* dst = sE + code * 36 + q;
            dst[0]  = v.x;
            dst[8]  = v.y;
            dst[16] = v.z;
            dst[24] = v.w;
        }
    }
    // --- esq + block max ---
    float em = 0.f;
    #pragma unroll
    for (int i = 0; i < 2; i++) {
        int k = t + i * 512;
        float v = g_Esq[k];
        sq[k] = v;
        em = fmaxf(em, v);
    }
    #pragma unroll
    for (int o = 16; o; o >>= 1) em = fmaxf(em, __shfl_xor_sync(0xffffffffu, em, o));
    if (l == 0) smx[w] = em;

    // --- z row -> regs: zsq exact chain (dims 0..63 sequential, R2 order),
    //     bf16x2 pack kept in regs (zb) for shfl-based A-frag build ---
    const float* zrow = in + b * 65536 + p;
    u32 zb[32];
    float zsq = 0.f, prev = 0.f;
    #pragma unroll
    for (int c = 0; c < 64; c++) {
        float v = __ldg(zrow + c * 1024);
        zsq = fmaf(v, v, zsq);
        if (c & 1) {
            u32 pr;  // lo = even dim, hi = odd dim
            asm("cvt.rn.bf16x2.f32 %0, %1, %2;" : "=r"(pr) : "f"(v), "f"(prev));
            zb[c >> 1] = pr;
        } else prev = v;
    }
    scnt[t] = 0;
    __syncthreads();

    float emax = smx[0];
    #pragma unroll
    for (int i = 1; i < 16; i++) emax = fmaxf(emax, smx[i]);

    // --- A fragments via intra-warp shfl: warp w owns rows rb..rb+31, which
    //     are exactly this warp's lanes. Values identical to R11's layout. ---
    u32 A[2][4][4];
    const int rb = w * 32;
    #pragma unroll
    for (int m = 0; m < 2; m++)
        #pragma unroll
        for (int ks = 0; ks < 4; ks++) {
            const int s0 = m * 16 + (l >> 2);
            const int s1 = s0 + 8;
            u32 a0 = 0, a1 = 0, a2 = 0, a3 = 0;
            #pragma unroll
            for (int c = 0; c < 4; c++) {
                u32 v0 = __shfl_sync(0xffffffffu, zb[ks * 8 + c],     s0);
                u32 v1 = __shfl_sync(0xffffffffu, zb[ks * 8 + c],     s1);
                u32 v2 = __shfl_sync(0xffffffffu, zb[ks * 8 + c + 4], s0);
                u32 v3 = __shfl_sync(0xffffffffu, zb[ks * 8 + c + 4], s1);
                if ((l & 3) == c) { a0 = v0; a1 = v1; a2 = v2; a3 = v3; }
            }
            A[m][ks][0] = a0; A[m][ks][1] = a1;
            A[m][ks][2] = a2; A[m][ks][3] = a3;
        }

    // --- per-thread row slots (D-frag rows); szq via shfl ---
    int   srow[4];
    float szq4[4], marg[4], rmin[4], thr4[4];
    #pragma unroll
    for (int m = 0; m < 2; m++)
        #pragma unroll
        for (int rh = 0; rh < 2; rh++) {
            int s = m * 2 + rh;
            int lane = m * 16 + (l >> 2) + 8 * rh;
            srow[s] = rb + lane;
            szq4[s] = __shfl_sync(0xffffffffu, zsq, lane);
            // MARGIN >= 2*|d_bf - d_exact|max ~ 2*2^-8*||z||*||e||max (+slop)
            marg[s] = 0.02f * sqrtf(szq4[s] * emax);
            rmin[s] = 3.4e38f;
            thr4[s] = 3.4e38f;
        }

    // ====== SINGLE PASS: min + collect; it==NIT revisits tiles 0-1 ======
    // Collects use the threshold from the PREVIOUS quad-sync (stale ->
    // conservative -> over-collects only). Iteration 0 has thr=inf so its
    // collection is disabled; its tiles are revisited at the end against the
    // final threshold (rmin is NOT re-updated there; values are identical).
    for (int it = 0; it <= NIT; it++) {
        const int nt = (it == NIT) ? 0 : it * 2;
        const int k0a = nt * 8 + (l & 3) * 2;
        const int k0b = k0a + 8;
        const u32* bp0 = sE + (nt * 8 + (l >> 2)) * 36 + (l & 3) * 8;
        const u32* bp1 = bp0 + 8 * 36;
        uint4 x0 = *(const uint4*)(bp0);
        uint4 x1 = *(const uint4*)(bp0 + 4);
        uint4 y0 = *(const uint4*)(bp1);
        uint4 y1 = *(const uint4*)(bp1 + 4);
        u32 B0[4][2] = {{x0.x,x0.y},{x0.z,x0.w},{x1.x,x1.y},{x1.z,x1.w}};
        u32 B1[4][2] = {{y0.x,y0.y},{y0.z,y0.w},{y1.x,y1.y},{y1.z,y1.w}};
        float D0a[4] = {0,0,0,0}, D1a[4] = {0,0,0,0};
        float D0b[4] = {0,0,0,0}, D1b[4] = {0,0,0,0};
        #pragma unroll
        for (int ks = 0; ks < 4; ks++) {   // 4 independent dependent-chains
            mma16816(D0a, A[0][ks], B0[ks]);
            mma16816(D1a, A[1][ks], B0[ks]);
            mma16816(D0b, A[0][ks], B1[ks]);
            mma16816(D1b, A[1][ks], B1[ks]);
        }
        const float ta0 = sq[k0a], ta1 = sq[k0a + 1];
        const float tb0 = sq[k0b], tb1 = sq[k0b + 1];
        #pragma unroll
        for (int m = 0; m < 2; m++) {
            const float* Da = m ? D1a : D0a;
            const float* Db = m ? D1b : D0b;
            #pragma unroll
            for (int rh = 0; rh < 2; rh++) {
                const int s = m * 2 + rh;
                float d0 = fmaf(-2.f, Da[rh * 2],     szq4[s] + ta0);
                float d1 = fmaf(-2.f, Da[rh * 2 + 1], szq4[s] + ta1);
                float d2 = fmaf(-2.f, Db[rh * 2],     szq4[s] + tb0);
                float d3 = fmaf(-2.f, Db[rh * 2 + 1], szq4[s] + tb1);
                if (it > 0) {
                    if (d0 <= thr4[s]) {
                        int ix = atomicAdd(&scnt[srow[s]], 1);
                        if (ix < CAP) scand[srow[s] * CAP + ix] = (u16)k0a;
                    }
                    if (d1 <= thr4[s]) {
                        int ix = atomicAdd(&scnt[srow[s]], 1);
                        if (ix < CAP) scand[srow[s] * CAP + ix] = (u16)(k0a + 1);
                    }
                    if (d2 <= thr4[s]) {
                        int ix = atomicAdd(&scnt[srow[s]], 1);
                        if (ix < CAP) scand[srow[s] * CAP + ix] = (u16)k0b;
                    }
                    if (d3 <= thr4[s]) {
                        int ix = atomicAdd(&scnt[srow[s]], 1);
                        if (ix < CAP) scand[srow[s] * CAP + ix] = (u16)(k0b + 1);
                    }
                }
                rmin[s] = fminf(rmin[s],
                                fminf(fminf(d0, d1), fminf(d2, d3)));
            }
        }
        // quad-sync the row min + refresh thresholds (skip after revisit)
        if (it < NIT) {
            #pragma unroll
            for (int s = 0; s < 4; s++) {
                float v = rmin[s];
                v = fminf(v, __shfl_xor_sync(0xffffffffu, v, 1));
                v = fminf(v, __shfl_xor_sync(0xffffffffu, v, 2));
                rmin[s] = v;
                thr4[s] = v + marg[s];
            }
        }
    }
    __syncthreads();

    // --- exact refine (thread t <-> row n). R2 bit chain + explicit tie-break.
    float zv[64];
    #pragma unroll
    for (int c = 0; c < 64; c++) zv[c] = __ldg(zrow + c * 1024);

    const int cr = scnt[t];
    float best = 3.4e38f;
    int bi = 0;
    const int full = (cr > CAP);            // astronomically rare; still correct
    const int nev = full ? KCODES : cr;
    for (int i = 0; i < nev; i++) {
        const int k = full ? i : (int)scand[t * CAP + i];
        const float4* er = (const float4*)(E + k * 64);
        float c0 = 0.f, c1 = 0.f, c2 = 0.f, c3 = 0.f;
        #pragma unroll
        for (int j = 0; j < 16; j++) {
            float4 e4 = __ldg(er + j);
            c0 = fmaf(zv[4*j],     e4.x, c0);
            c1 = fmaf(zv[4*j + 1], e4.y, c1);
            c2 = fmaf(zv[4*j + 2], e4.z, c2);
            c3 = fmaf(zv[4*j + 3], e4.w, c3);
        }
        float s = __fadd_rn(__fadd_rn(c0, c2), __fadd_rn(c1, c3));
        float d = __fmaf_rn(-2.0f, s, __fadd_rn(zsq, sq[k]));
        if (d < best || (d == best && k < bi)) { best = d; bi = k; }
    }
    atomicAdd(&g_counts[bi], 1);

    // --- fused gather Zq + loss (bit-mimicking fl(z + fl(e - z))) ---
    float ls = 0.f;
    float* zq = out + 1 + b * 65536 + p;
    const float4* er = (const float4*)(E + bi * 64);
    #pragma unroll
    for (int j = 0; j < 16; j++) {
        float4 e4 = __ldg(er + j);
        float ev[4] = {e4.x, e4.y, e4.z, e4.w};
        #pragma unroll
        for (int m = 0; m < 4; m++) {
            float z = zv[4*j + m];
            float diff = __fsub_rn(ev[m], z);
            ls = fmaf(diff, diff, ls);
            zq[(4*j + m) * 1024] = __fadd_rn(z, diff);
        }
    }
    #pragma unroll
    for (int o = 16; o; o >>= 1) ls += __shfl_xor_sync(0xffffffffu, ls, o);
    __syncthreads();                 // emax reads long done; reuse smx
    if (l == 0) smx[w] = ls;
    __syncthreads();
    if (t == 0) {
        float s = 0.f;
        #pragma unroll
        for (int i = 0; i < 16; i++) s += smx[i];
        atomicAdd(&g_loss, (double)s);
        __threadfence();
        int old = atomicAdd(&g_done, 1);
        s_islast = (old == NCTA - 1);
    }
    __syncthreads();

    // --- last CTA: finalize (perplexity + scalars) ---
    if (s_islast) {
        __threadfence();
        float v = 0.f;
        #pragma unroll
        for (int i = 0; i < 2; i++) {
            int k = t + i * 512;
            float cnt = (float)g_counts[k];
            float pr = cnt * (1.0f / 65536.0f);
            v = fmaf(pr, log2f(pr + 1e-10f), v);
        }
        #pragma unroll
        for (int o = 16; o; o >>= 1) v += __shfl_xor_sync(0xffffffffu, v, o);
        if (l == 0) smx[w] = v;
        __syncthreads();
        if (t == 0) {
            float x = 0.f;
            #pragma unroll
            for (int i = 0; i < 16; i++) x += smx[i];
            float entropy = -x;
            float perp = exp2f(entropy);
            float lv = (float)(g_loss * (1.0 / 4194304.0));
            out[0] = lv + 0.25f * lv;
            out[1 + NROWS * DIM]     = lv;
            out[1 + NROWS * DIM + 1] = lv;
            out[1 + NROWS * DIM + 2] = perp;
            g_done = 0;              // reset for graph replay determinism
        }
    }
}

// ---------------------------------------------------------------------------
extern "C" void kernel_launch(void* const* d_in, const int* in_sizes, int n_in,
                              void* d_out, int out_size) {
    const float* in = (const float*)d_in[0];
    const float* E  = (const float*)d_in[1];
    float* out = (float*)d_out;

    cudaFuncSetAttribute(vq_main, cudaFuncAttributeMaxDynamicSharedMemorySize,
                         SMEM_SZ);
    prep_kernel<<<32, 32>>>(E);
    vq_main<<<NCTA, THREADS, SMEM_SZ>>>(in, E, out);
}

// round 13
// speedup vs baseline: 1.1211x; 1.1211x over previous
#include <cuda_runtime.h>
#include <cstdint>

typedef unsigned int u32;
typedef unsigned short u16;

#define KCODES 1024
#define DIM 64
#define NROWS 65536
#define THREADS 512
#define RPC 512          // rows per CTA
#define NT 128           // n-tiles of 8 codes
#define NIT (NT / 2)     // GEMM iterations (2 tiles each)
#define CAP 16           // candidate cap per row (overflow -> exact full scan)
#define NCTA 128

// Scratch (no device allocation allowed -> __device__ globals)
__device__ int    g_counts[KCODES];
__device__ float  g_Esq[KCODES];
__device__ double g_loss;
__device__ int    g_done;
__device__ __align__(16) u32 g_Ebf[KCODES * 32];  // bf16x2-packed codebook

// ---------------------------------------------------------------------------
// SMEM layout (bytes). E rows 36 u32 (144B) in PERMUTED frag order:
//   sE[code*36 + (j&3)*8 + q] holds original k-pair u32 j = 4q + (j&3),
// so one lane's 8 B-frag words for a tile are 8 contiguous u32 -> 2x LDS.128.
// ---------------------------------------------------------------------------
#define SE_OFF    0          // E bf16 [1024][36 u32]            147456
#define SQ_OFF    147456     // esq f32 [1024]                     4096
#define SQH_OFF   151552     // esq/2 f32 [1024]                   4096
#define SCAND_OFF 155648     // cand u16 [512][CAP]               16384
#define SCNT_OFF  172032     // counts int [512]                   2048
#define SMX_OFF   174080     // misc f32 [16] (emax / loss)          64
#define SMEM_SZ   174144

// ---------------------------------------------------------------------------
// Kernel 1: esq (exact fp32 sequential chain - DO NOT reorder, bit-feeds the
// verified d chain) + bf16x2-pack E + zero accumulators. 32x32 for latency.
// ---------------------------------------------------------------------------
__global__ void prep_kernel(const float* __restrict__ E) {
    int k = blockIdx.x * 32 + threadIdx.x;
    if (k < KCODES) {
        float e[64];
        const float4* er = (const float4*)(E + k * DIM);
        #pragma unroll
        for (int i = 0; i < 16; i++) {
            float4 v = er[i];
            e[4*i] = v.x; e[4*i+1] = v.y; e[4*i+2] = v.z; e[4*i+3] = v.w;
        }
        float s = 0.f;
        #pragma unroll
        for (int d = 0; d < 64; d++) s = fmaf(e[d], e[d], s);
        g_Esq[k] = s;
        g_counts[k] = 0;
        #pragma unroll
        for (int i = 0; i < 32; i++) {
            u32 pr;  // lo = dim 2i, hi = dim 2i+1
            asm("cvt.rn.bf16x2.f32 %0, %1, %2;" : "=r"(pr) : "f"(e[2*i+1]), "f"(e[2*i]));
            g_Ebf[k * 32 + i] = pr;
        }
    }
    if (k == 0) { g_loss = 0.0; g_done = 0; }
}

// ---------------------------------------------------------------------------
// m16n8k16 bf16 mma, fp32 accumulate (base PTX, works on plain sm_103)
// ---------------------------------------------------------------------------
__device__ __forceinline__ void mma16816(float d[4], const u32 a[4], const u32 b[2]) {
    asm("mma.sync.aligned.m16n8k16.row.col.f32.bf16.bf16.f32 "
        "{%0,%1,%2,%3}, {%4,%5,%6,%7}, {%8,%9}, {%0,%1,%2,%3};"
        : "+f"(d[0]), "+f"(d[1]), "+f"(d[2]), "+f"(d[3])
        : "r"(a[0]), "r"(a[1]), "r"(a[2]), "r"(a[3]), "r"(b[0]), "r"(b[1]));
}

// ---------------------------------------------------------------------------
// Kernel 2: bf16 HMMA two-pass, ARGMAX domain (s' = z.e - esq/2; max s' ==
// min d since zsq is row-constant). Pass 1: per-row max with B-LDS software
// pipelining; pass 2: collect vs final max - margin'. -> exact refine ->
// fused gather/loss -> last-CTA finalize. Exact path = R2-verified bit chain.
// ---------------------------------------------------------------------------
__global__ void __launch_bounds__(THREADS, 1)
vq_main(const float* __restrict__ in, const float* __restrict__ E,
        float* __restrict__ out) {
    extern __shared__ __align__(16) char S[];
    u32*   sE    = (u32*)(S + SE_OFF);
    float* sq    = (float*)(S + SQ_OFF);
    float* sqh   = (float*)(S + SQH_OFF);
    u16*   scand = (u16*)(S + SCAND_OFF);
    int*   scnt  = (int*)(S + SCNT_OFF);
    float* smx   = (float*)(S + SMX_OFF);
    __shared__ int s_islast;

    const int t = threadIdx.x;
    const int w = t >> 5, l = t & 31;
    const int n = blockIdx.x * RPC + t;
    const int b = n >> 10, p = n & 1023;

    // --- stage E permuted: sE[code*36 + c*8 + q] = component c of uint4 q ---
    {
        const uint4* esrc = (const uint4*)g_Ebf;
        #pragma unroll
        for (int i = 0; i < 16; i++) {
            int lin = t + i * 512;              // uint4 index
            int code = lin >> 3, q = lin & 7;
            uint4 v = esrc[lin];
            u32* dst = sE + code * 36 + q;
            dst[0]  = v.x;
            dst[8]  = v.y;
            dst[16] = v.z;
            dst[24] = v.w;
        }
    }
    // --- esq (+half) + block max ---
    float em = 0.f;
    #pragma unroll
    for (int i = 0; i < 2; i++) {
        int k = t + i * 512;
        float v = g_Esq[k];
        sq[k] = v;
        sqh[k] = 0.5f * v;
        em = fmaxf(em, v);
    }
    #pragma unroll
    for (int o = 16; o; o >>= 1) em = fmaxf(em, __shfl_xor_sync(0xffffffffu, em, o));
    if (l == 0) smx[w] = em;

    // --- z row -> regs: zsq exact chain (dims 0..63 sequential, R2 order),
    //     bf16x2 pack kept in regs (zb) for shfl-based A-frag build ---
    const float* zrow = in + b * 65536 + p;
    u32 zb[32];
    float zsq = 0.f, prev = 0.f;
    #pragma unroll
    for (int c = 0; c < 64; c++) {
        float v = __ldg(zrow + c * 1024);
        zsq = fmaf(v, v, zsq);
        if (c & 1) {
            u32 pr;  // lo = even dim, hi = odd dim
            asm("cvt.rn.bf16x2.f32 %0, %1, %2;" : "=r"(pr) : "f"(v), "f"(prev));
            zb[c >> 1] = pr;
        } else prev = v;
    }
    scnt[t] = 0;
    __syncthreads();

    float emax = smx[0];
    #pragma unroll
    for (int i = 1; i < 16; i++) emax = fmaxf(emax, smx[i]);

    // --- A fragments via intra-warp shfl: warp w owns rows rb..rb+31, which
    //     are exactly this warp's lanes. Values identical to R11's layout. ---
    u32 A[2][4][4];
    const int rb = w * 32;
    #pragma unroll
    for (int m = 0; m < 2; m++)
        #pragma unroll
        for (int ks = 0; ks < 4; ks++) {
            const int s0 = m * 16 + (l >> 2);
            const int s1 = s0 + 8;
            u32 a0 = 0, a1 = 0, a2 = 0, a3 = 0;
            #pragma unroll
            for (int c = 0; c < 4; c++) {
                u32 v0 = __shfl_sync(0xffffffffu, zb[ks * 8 + c],     s0);
                u32 v1 = __shfl_sync(0xffffffffu, zb[ks * 8 + c],     s1);
                u32 v2 = __shfl_sync(0xffffffffu, zb[ks * 8 + c + 4], s0);
                u32 v3 = __shfl_sync(0xffffffffu, zb[ks * 8 + c + 4], s1);
                if ((l & 3) == c) { a0 = v0; a1 = v1; a2 = v2; a3 = v3; }
            }
            A[m][ks][0] = a0; A[m][ks][1] = a1;
            A[m][ks][2] = a2; A[m][ks][3] = a3;
        }

    // --- per-thread row slots (D-frag rows); szq via shfl ---
    int   srow[4];
    float szq4[4], rmax[4];
    #pragma unroll
    for (int m = 0; m < 2; m++)
        #pragma unroll
        for (int rh = 0; rh < 2; rh++) {
            int s = m * 2 + rh;
            int lane = m * 16 + (l >> 2) + 8 * rh;
            srow[s] = rb + lane;
            szq4[s] = __shfl_sync(0xffffffffu, zsq, lane);
            rmax[s] = -3.4e38f;
        }

    const int bbase = (l >> 2) * 36 + (l & 3) * 8;   // per-thread B offset

    // ============ PASS 1: bf16 max of s'; B double-buffer pipelined ========
    {
        uint4 cx0 = *(const uint4*)(sE + bbase);
        uint4 cx1 = *(const uint4*)(sE + bbase + 4);
        uint4 cy0 = *(const uint4*)(sE + bbase + 288);
        uint4 cy1 = *(const uint4*)(sE + bbase + 292);
        for (int it = 0; it < NIT; it++) {
            // prefetch next iteration's B (clamped index: last prefetch dead)
            const int nit = (it + 1 < NIT) ? (it + 1) : it;
            const u32* np = sE + bbase + nit * 576;
            uint4 nx0 = *(const uint4*)(np);
            uint4 nx1 = *(const uint4*)(np + 4);
            uint4 ny0 = *(const uint4*)(np + 288);
            uint4 ny1 = *(const uint4*)(np + 292);

            u32 B0[4][2] = {{cx0.x,cx0.y},{cx0.z,cx0.w},{cx1.x,cx1.y},{cx1.z,cx1.w}};
            u32 B1[4][2] = {{cy0.x,cy0.y},{cy0.z,cy0.w},{cy1.x,cy1.y},{cy1.z,cy1.w}};
            float D0a[4] = {0,0,0,0}, D1a[4] = {0,0,0,0};
            float D0b[4] = {0,0,0,0}, D1b[4] = {0,0,0,0};
            #pragma unroll
            for (int ks = 0; ks < 4; ks++) {   // 4 independent chains
                mma16816(D0a, A[0][ks], B0[ks]);
                mma16816(D1a, A[1][ks], B0[ks]);
                mma16816(D0b, A[0][ks], B1[ks]);
                mma16816(D1b, A[1][ks], B1[ks]);
            }
            const int k0a = it * 16 + (l & 3) * 2;
            const int k0b = k0a + 8;
            const float ha0 = sqh[k0a], ha1 = sqh[k0a + 1];
            const float hb0 = sqh[k0b], hb1 = sqh[k0b + 1];
            #pragma unroll
            for (int m = 0; m < 2; m++) {
                const float* Da = m ? D1a : D0a;
                const float* Db = m ? D1b : D0b;
                #pragma unroll
                for (int rh = 0; rh < 2; rh++) {
                    const int s = m * 2 + rh;
                    float s0 = Da[rh * 2]     - ha0;
                    float s1 = Da[rh * 2 + 1] - ha1;
                    float s2 = Db[rh * 2]     - hb0;
                    float s3 = Db[rh * 2 + 1] - hb1;
                    rmax[s] = fmaxf(rmax[s],
                                    fmaxf(fmaxf(s0, s1), fmaxf(s2, s3)));
                }
            }
            cx0 = nx0; cx1 = nx1; cy0 = ny0; cy1 = ny1;
        }
    }
    // final per-row max across the 4 sibling lanes; threshold in s'-domain:
    // collect s' >= max - marg', marg' = marg/2 (d = zsq + 2*(esq/2 - s')).
    float thr4[4];
    #pragma unroll
    for (int s = 0; s < 4; s++) {
        float v = rmax[s];
        v = fmaxf(v, __shfl_xor_sync(0xffffffffu, v, 1));
        v = fmaxf(v, __shfl_xor_sync(0xffffffffu, v, 2));
        thr4[s] = v - 0.01f * sqrtf(szq4[s] * emax);
    }

    // ============ PASS 2: recompute + collect vs final threshold ============
    {
        uint4 cx0 = *(const uint4*)(sE + bbase);
        uint4 cx1 = *(const uint4*)(sE + bbase + 4);
        uint4 cy0 = *(const uint4*)(sE + bbase + 288);
        uint4 cy1 = *(const uint4*)(sE + bbase + 292);
        for (int it = 0; it < NIT; it++) {
            const int nit = (it + 1 < NIT) ? (it + 1) : it;
            const u32* np = sE + bbase + nit * 576;
            uint4 nx0 = *(const uint4*)(np);
            uint4 nx1 = *(const uint4*)(np + 4);
            uint4 ny0 = *(const uint4*)(np + 288);
            uint4 ny1 = *(const uint4*)(np + 292);

            u32 B0[4][2] = {{cx0.x,cx0.y},{cx0.z,cx0.w},{cx1.x,cx1.y},{cx1.z,cx1.w}};
            u32 B1[4][2] = {{cy0.x,cy0.y},{cy0.z,cy0.w},{cy1.x,cy1.y},{cy1.z,cy1.w}};
            float D0a[4] = {0,0,0,0}, D1a[4] = {0,0,0,0};
            float D0b[4] = {0,0,0,0}, D1b[4] = {0,0,0,0};
            #pragma unroll
            for (int ks = 0; ks < 4; ks++) {
                mma16816(D0a, A[0][ks], B0[ks]);
                mma16816(D1a, A[1][ks], B0[ks]);
                mma16816(D0b, A[0][ks], B1[ks]);
                mma16816(D1b, A[1][ks], B1[ks]);
            }
            const int k0a = it * 16 + (l & 3) * 2;
            const int k0b = k0a + 8;
            const float ha0 = sqh[k0a], ha1 = sqh[k0a + 1];
            const float hb0 = sqh[k0b], hb1 = sqh[k0b + 1];
            #pragma unroll
            for (int m = 0; m < 2; m++) {
                const float* Da = m ? D1a : D0a;
                const float* Db = m ? D1b : D0b;
                #pragma unroll
                for (int rh = 0; rh < 2; rh++) {
                    const int s = m * 2 + rh;
                    float s0 = Da[rh * 2]     - ha0;
                    float s1 = Da[rh * 2 + 1] - ha1;
                    float s2 = Db[rh * 2]     - hb0;
                    float s3 = Db[rh * 2 + 1] - hb1;
                    if (s0 >= thr4[s]) {
                        int ix = atomicAdd(&scnt[srow[s]], 1);
                        if (ix < CAP) scand[srow[s] * CAP + ix] = (u16)k0a;
                    }
                    if (s1 >= thr4[s]) {
                        int ix = atomicAdd(&scnt[srow[s]], 1);
                        if (ix < CAP) scand[srow[s] * CAP + ix] = (u16)(k0a + 1);
                    }
                    if (s2 >= thr4[s]) {
                        int ix = atomicAdd(&scnt[srow[s]], 1);
                        if (ix < CAP) scand[srow[s] * CAP + ix] = (u16)k0b;
                    }
                    if (s3 >= thr4[s]) {
                        int ix = atomicAdd(&scnt[srow[s]], 1);
                        if (ix < CAP) scand[srow[s] * CAP + ix] = (u16)(k0b + 1);
                    }
                }
            }
            cx0 = nx0; cx1 = nx1; cy0 = ny0; cy1 = ny1;
        }
    }
    __syncthreads();

    // --- exact refine (thread t <-> row n). R2 bit chain + explicit tie-break.
    float zv[64];
    #pragma unroll
    for (int c = 0; c < 64; c++) zv[c] = __ldg(zrow + c * 1024);

    const int cr = scnt[t];
    float best = 3.4e38f;
    int bi = 0;
    const int full = (cr > CAP);            // astronomically rare; still correct
    const int nev = full ? KCODES : cr;
    for (int i = 0; i < nev; i++) {
        const int k = full ? i : (int)scand[t * CAP + i];
        const float4* er = (const float4*)(E + k * 64);
        float c0 = 0.f, c1 = 0.f, c2 = 0.f, c3 = 0.f;
        #pragma unroll
        for (int j = 0; j < 16; j++) {
            float4 e4 = __ldg(er + j);
            c0 = fmaf(zv[4*j],     e4.x, c0);
            c1 = fmaf(zv[4*j + 1], e4.y, c1);
            c2 = fmaf(zv[4*j + 2], e4.z, c2);
            c3 = fmaf(zv[4*j + 3], e4.w, c3);
        }
        float s = __fadd_rn(__fadd_rn(c0, c2), __fadd_rn(c1, c3));
        float d = __fmaf_rn(-2.0f, s, __fadd_rn(zsq, sq[k]));
        if (d < best || (d == best && k < bi)) { best = d; bi = k; }
    }
    atomicAdd(&g_counts[bi], 1);

    // --- fused gather Zq + loss (bit-mimicking fl(z + fl(e - z))) ---
    float ls = 0.f;
    float* zq = out + 1 + b * 65536 + p;
    const float4* er = (const float4*)(E + bi * 64);
    #pragma unroll
    for (int j = 0; j < 16; j++) {
        float4 e4 = __ldg(er + j);
        float ev[4] = {e4.x, e4.y, e4.z, e4.w};
        #pragma unroll
        for (int m = 0; m < 4; m++) {
            float z = zv[4*j + m];
            float diff = __fsub_rn(ev[m], z);
            ls = fmaf(diff, diff, ls);
            zq[(4*j + m) * 1024] = __fadd_rn(z, diff);
        }
    }
    #pragma unroll
    for (int o = 16; o; o >>= 1) ls += __shfl_xor_sync(0xffffffffu, ls, o);
    __syncthreads();                 // emax reads long done; reuse smx
    if (l == 0) smx[w] = ls;
    __syncthreads();
    if (t == 0) {
        float s = 0.f;
        #pragma unroll
        for (int i = 0; i < 16; i++) s += smx[i];
        atomicAdd(&g_loss, (double)s);
        __threadfence();
        int old = atomicAdd(&g_done, 1);
        s_islast = (old == NCTA - 1);
    }
    __syncthreads();

    // --- last CTA: finalize (perplexity + scalars) ---
    if (s_islast) {
        __threadfence();
        float v = 0.f;
        #pragma unroll
        for (int i = 0; i < 2; i++) {
            int k = t + i * 512;
            float cnt = (float)g_counts[k];
            float pr = cnt * (1.0f / 65536.0f);
            v = fmaf(pr, log2f(pr + 1e-10f), v);
        }
        #pragma unroll
        for (int o = 16; o; o >>= 1) v += __shfl_xor_sync(0xffffffffu, v, o);
        if (l == 0) smx[w] = v;
        __syncthreads();
        if (t == 0) {
            float x = 0.f;
            #pragma unroll
            for (int i = 0; i < 16; i++) x += smx[i];
            float entropy = -x;
            float perp = exp2f(entropy);
            float lv = (float)(g_loss * (1.0 / 4194304.0));
            out[0] = lv + 0.25f * lv;
            out[1 + NROWS * DIM]     = lv;
            out[1 + NROWS * DIM + 1] = lv;
            out[1 + NROWS * DIM + 2] = perp;
            g_done = 0;              // reset for graph replay determinism
        }
    }
}

// ---------------------------------------------------------------------------
extern "C" void kernel_launch(void* const* d_in, const int* in_sizes, int n_in,
                              void* d_out, int out_size) {
    const float* in = (const float*)d_in[0];
    const float* E  = (const float*)d_in[1];
    float* out = (float*)d_out;

    cudaFuncSetAttribute(vq_main, cudaFuncAttributeMaxDynamicSharedMemorySize,
                         SMEM_SZ);
    prep_kernel<<<32, 32>>>(E);
    vq_main<<<NCTA, THREADS, SMEM_SZ>>>(in, E, out);
}

// round 14
// speedup vs baseline: 1.1839x; 1.0560x over previous
#include <cuda_runtime.h>
#include <cstdint>

typedef unsigned int u32;
typedef unsigned short u16;

#define KCODES 1024
#define DIM 64
#define NROWS 65536
#define THREADS 512
#define NT 128           // n-tiles of 8 codes
#define NIT (NT / 2)     // GEMM iterations (2 tiles each)
#define CAP 16           // candidate cap per row (overflow -> exact full scan)
#define NCTA 152         // one CTA per SM; warp-granular work units
#define NUNITS 2048      // 65536 rows / 32

// Scratch (no device allocation allowed -> __device__ globals)
__device__ int    g_counts[KCODES];
__device__ float  g_Esq[KCODES];
__device__ double g_loss;
__device__ int    g_done;
__device__ __align__(16) u32 g_Ebf[KCODES * 32];  // bf16x2-packed codebook

// ---------------------------------------------------------------------------
// SMEM layout (bytes). E rows 36 u32 (144B) in PERMUTED frag order:
//   sE[code*36 + (j&3)*8 + q] holds original k-pair u32 j = 4q + (j&3),
// so one lane's 8 B-frag words for a tile are 8 contiguous u32 -> 2x LDS.128.
// ---------------------------------------------------------------------------
#define SE_OFF    0          // E bf16 [1024][36 u32]            147456
#define SQ_OFF    147456     // esq f32 [1024]                     4096
#define SQH_OFF   151552     // esq/2 f32 [1024]                   4096
#define SCAND_OFF 155648     // cand u16 [512][CAP]               16384
#define SCNT_OFF  172032     // counts int [512]                   2048
#define SMX_OFF   174080     // misc f32 [16] (emax / loss)          64
#define SMEM_SZ   174144

// ---------------------------------------------------------------------------
// Kernel 1: esq (exact fp32 sequential chain - DO NOT reorder, bit-feeds the
// verified d chain) + bf16x2-pack E + zero accumulators. 32x32 for latency.
// ---------------------------------------------------------------------------
__global__ void prep_kernel(const float* __restrict__ E) {
    int k = blockIdx.x * 32 + threadIdx.x;
    if (k < KCODES) {
        float e[64];
        const float4* er = (const float4*)(E + k * DIM);
        #pragma unroll
        for (int i = 0; i < 16; i++) {
            float4 v = er[i];
            e[4*i] = v.x; e[4*i+1] = v.y; e[4*i+2] = v.z; e[4*i+3] = v.w;
        }
        float s = 0.f;
        #pragma unroll
        for (int d = 0; d < 64; d++) s = fmaf(e[d], e[d], s);
        g_Esq[k] = s;
        g_counts[k] = 0;
        #pragma unroll
        for (int i = 0; i < 32; i++) {
            u32 pr;  // lo = dim 2i, hi = dim 2i+1
            asm("cvt.rn.bf16x2.f32 %0, %1, %2;" : "=r"(pr) : "f"(e[2*i+1]), "f"(e[2*i]));
            g_Ebf[k * 32 + i] = pr;
        }
    }
    if (k == 0) { g_loss = 0.0; g_done = 0; }
}

// ---------------------------------------------------------------------------
// m16n8k16 bf16 mma, fp32 accumulate (base PTX, works on plain sm_103)
// ---------------------------------------------------------------------------
__device__ __forceinline__ void mma16816(float d[4], const u32 a[4], const u32 b[2]) {
    asm("mma.sync.aligned.m16n8k16.row.col.f32.bf16.bf16.f32 "
        "{%0,%1,%2,%3}, {%4,%5,%6,%7}, {%8,%9}, {%0,%1,%2,%3};"
        : "+f"(d[0]), "+f"(d[1]), "+f"(d[2]), "+f"(d[3])
        : "r"(a[0]), "r"(a[1]), "r"(a[2]), "r"(a[3]), "r"(b[0]), "r"(b[1]));
}

// ---------------------------------------------------------------------------
// Kernel 2: warp-autonomous units of 32 rows; unit = blockIdx + 152*warp
// (interleaved so every SM keeps 13-14 active warps). Per unit: bf16 HMMA
// two-pass argmax (pass 1: per-row max, B-LDS pipelined; pass 2: collect vs
// final max - margin') -> warp-local exact refine (R2 bit chain) -> fused
// gather/loss. Last-CTA finalize.
// ---------------------------------------------------------------------------
__global__ void __launch_bounds__(THREADS, 1)
vq_main(const float* __restrict__ in, const float* __restrict__ E,
        float* __restrict__ out) {
    extern __shared__ __align__(16) char S[];
    u32*   sE    = (u32*)(S + SE_OFF);
    float* sq    = (float*)(S + SQ_OFF);
    float* sqh   = (float*)(S + SQH_OFF);
    u16*   scand = (u16*)(S + SCAND_OFF);
    int*   scnt  = (int*)(S + SCNT_OFF);
    float* smx   = (float*)(S + SMX_OFF);
    __shared__ int s_islast;

    const int t = threadIdx.x;
    const int w = t >> 5, l = t & 31;
    const int gw = blockIdx.x + NCTA * w;   // this warp's 32-row unit
    const bool act = (gw < NUNITS);
    const int n = gw * 32 + l;              // this lane's row (valid iff act)
    const int b = n >> 10, p = n & 1023;
    const float* zrow = in + b * 65536 + p; // deref'd only when act

    // --- stage E permuted: sE[code*36 + c*8 + q] = component c of uint4 q ---
    {
        const uint4* esrc = (const uint4*)g_Ebf;
        #pragma unroll
        for (int i = 0; i < 16; i++) {
            int lin = t + i * 512;              // uint4 index
            int code = lin >> 3, q = lin & 7;
            uint4 v = esrc[lin];
            u32* dst = sE + code * 36 + q;
            dst[0]  = v.x;
            dst[8]  = v.y;
            dst[16] = v.z;
            dst[24] = v.w;
        }
    }
    // --- esq (+half) + block max ---
    float em = 0.f;
    #pragma unroll
    for (int i = 0; i < 2; i++) {
        int k = t + i * 512;
        float v = g_Esq[k];
        sq[k] = v;
        sqh[k] = 0.5f * v;
        em = fmaxf(em, v);
    }
    #pragma unroll
    for (int o = 16; o; o >>= 1) em = fmaxf(em, __shfl_xor_sync(0xffffffffu, em, o));
    if (l == 0) smx[w] = em;
    scnt[t] = 0;
    __syncthreads();

    float emax = smx[0];
    #pragma unroll
    for (int i = 1; i < 16; i++) emax = fmaxf(emax, smx[i]);

    float ls = 0.f;    // loss partial (0 for inactive warps)

    if (act) {
        // --- z row -> regs: zsq exact chain (dims 0..63 sequential, R2 order),
        //     bf16x2 pack kept in regs (zb) for shfl-based A-frag build ---
        u32 zb[32];
        float zsq = 0.f, prev = 0.f;
        #pragma unroll
        for (int c = 0; c < 64; c++) {
            float v = __ldg(zrow + c * 1024);
            zsq = fmaf(v, v, zsq);
            if (c & 1) {
                u32 pr;  // lo = even dim, hi = odd dim
                asm("cvt.rn.bf16x2.f32 %0, %1, %2;" : "=r"(pr) : "f"(v), "f"(prev));
                zb[c >> 1] = pr;
            } else prev = v;
        }

        // --- A fragments via intra-warp shfl: unit rows are this warp's lanes ---
        u32 A[2][4][4];
        #pragma unroll
        for (int m = 0; m < 2; m++)
            #pragma unroll
            for (int ks = 0; ks < 4; ks++) {
                const int s0 = m * 16 + (l >> 2);
                const int s1 = s0 + 8;
                u32 a0 = 0, a1 = 0, a2 = 0, a3 = 0;
                #pragma unroll
                for (int c = 0; c < 4; c++) {
                    u32 v0 = __shfl_sync(0xffffffffu, zb[ks * 8 + c],     s0);
                    u32 v1 = __shfl_sync(0xffffffffu, zb[ks * 8 + c],     s1);
                    u32 v2 = __shfl_sync(0xffffffffu, zb[ks * 8 + c + 4], s0);
                    u32 v3 = __shfl_sync(0xffffffffu, zb[ks * 8 + c + 4], s1);
                    if ((l & 3) == c) { a0 = v0; a1 = v1; a2 = v2; a3 = v3; }
                }
                A[m][ks][0] = a0; A[m][ks][1] = a1;
                A[m][ks][2] = a2; A[m][ks][3] = a3;
            }

        // --- per-thread row slots (D-frag rows); szq via shfl ---
        int   srow[4];          // LOCAL slot index (w*32 + lane-of-row)
        float szq4[4], rmax[4];
        #pragma unroll
        for (int m = 0; m < 2; m++)
            #pragma unroll
            for (int rh = 0; rh < 2; rh++) {
                int s = m * 2 + rh;
                int lane = m * 16 + (l >> 2) + 8 * rh;
                srow[s] = w * 32 + lane;
                szq4[s] = __shfl_sync(0xffffffffu, zsq, lane);
                rmax[s] = -3.4e38f;
            }

        const int bbase = (l >> 2) * 36 + (l & 3) * 8;   // per-thread B offset

        // ============ PASS 1: bf16 max of s'; B double-buffer pipelined ====
        {
            uint4 cx0 = *(const uint4*)(sE + bbase);
            uint4 cx1 = *(const uint4*)(sE + bbase + 4);
            uint4 cy0 = *(const uint4*)(sE + bbase + 288);
            uint4 cy1 = *(const uint4*)(sE + bbase + 292);
            for (int it = 0; it < NIT; it++) {
                const int nit = (it + 1 < NIT) ? (it + 1) : it;
                const u32* np = sE + bbase + nit * 576;
                uint4 nx0 = *(const uint4*)(np);
                uint4 nx1 = *(const uint4*)(np + 4);
                uint4 ny0 = *(const uint4*)(np + 288);
                uint4 ny1 = *(const uint4*)(np + 292);

                u32 B0[4][2] = {{cx0.x,cx0.y},{cx0.z,cx0.w},{cx1.x,cx1.y},{cx1.z,cx1.w}};
                u32 B1[4][2] = {{cy0.x,cy0.y},{cy0.z,cy0.w},{cy1.x,cy1.y},{cy1.z,cy1.w}};
                float D0a[4] = {0,0,0,0}, D1a[4] = {0,0,0,0};
                float D0b[4] = {0,0,0,0}, D1b[4] = {0,0,0,0};
                #pragma unroll
                for (int ks = 0; ks < 4; ks++) {   // 4 independent chains
                    mma16816(D0a, A[0][ks], B0[ks]);
                    mma16816(D1a, A[1][ks], B0[ks]);
                    mma16816(D0b, A[0][ks], B1[ks]);
                    mma16816(D1b, A[1][ks], B1[ks]);
                }
                const int k0a = it * 16 + (l & 3) * 2;
                const int k0b = k0a + 8;
                const float ha0 = sqh[k0a], ha1 = sqh[k0a + 1];
                const float hb0 = sqh[k0b], hb1 = sqh[k0b + 1];
                #pragma unroll
                for (int m = 0; m < 2; m++) {
                    const float* Da = m ? D1a : D0a;
                    const float* Db = m ? D1b : D0b;
                    #pragma unroll
                    for (int rh = 0; rh < 2; rh++) {
                        const int s = m * 2 + rh;
                        float s0 = Da[rh * 2]     - ha0;
                        float s1 = Da[rh * 2 + 1] - ha1;
                        float s2 = Db[rh * 2]     - hb0;
                        float s3 = Db[rh * 2 + 1] - hb1;
                        rmax[s] = fmaxf(rmax[s],
                                        fmaxf(fmaxf(s0, s1), fmaxf(s2, s3)));
                    }
                }
                cx0 = nx0; cx1 = nx1; cy0 = ny0; cy1 = ny1;
            }
        }
        // final per-row max across the 4 sibling lanes; threshold in s'-domain:
        // collect s' >= max - marg', marg' = marg/2 (d = zsq + 2*(esq/2 - s')).
        float thr4[4];
        #pragma unroll
        for (int s = 0; s < 4; s++) {
            float v = rmax[s];
            v = fmaxf(v, __shfl_xor_sync(0xffffffffu, v, 1));
            v = fmaxf(v, __shfl_xor_sync(0xffffffffu, v, 2));
            thr4[s] = v - 0.01f * sqrtf(szq4[s] * emax);
        }

        // ============ PASS 2: recompute + collect vs final threshold ========
        {
            uint4 cx0 = *(const uint4*)(sE + bbase);
            uint4 cx1 = *(const uint4*)(sE + bbase + 4);
            uint4 cy0 = *(const uint4*)(sE + bbase + 288);
            uint4 cy1 = *(const uint4*)(sE + bbase + 292);
            for (int it = 0; it < NIT; it++) {
                const int nit = (it + 1 < NIT) ? (it + 1) : it;
                const u32* np = sE + bbase + nit * 576;
                uint4 nx0 = *(const uint4*)(np);
                uint4 nx1 = *(const uint4*)(np + 4);
                uint4 ny0 = *(const uint4*)(np + 288);
                uint4 ny1 = *(const uint4*)(np + 292);

                u32 B0[4][2] = {{cx0.x,cx0.y},{cx0.z,cx0.w},{cx1.x,cx1.y},{cx1.z,cx1.w}};
                u32 B1[4][2] = {{cy0.x,cy0.y},{cy0.z,cy0.w},{cy1.x,cy1.y},{cy1.z,cy1.w}};
                float D0a[4] = {0,0,0,0}, D1a[4] = {0,0,0,0};
                float D0b[4] = {0,0,0,0}, D1b[4] = {0,0,0,0};
                #pragma unroll
                for (int ks = 0; ks < 4; ks++) {
                    mma16816(D0a, A[0][ks], B0[ks]);
                    mma16816(D1a, A[1][ks], B0[ks]);
                    mma16816(D0b, A[0][ks], B1[ks]);
                    mma16816(D1b, A[1][ks], B1[ks]);
                }
                const int k0a = it * 16 + (l & 3) * 2;
                const int k0b = k0a + 8;
                const float ha0 = sqh[k0a], ha1 = sqh[k0a + 1];
                const float hb0 = sqh[k0b], hb1 = sqh[k0b + 1];
                #pragma unroll
                for (int m = 0; m < 2; m++) {
                    const float* Da = m ? D1a : D0a;
                    const float* Db = m ? D1b : D0b;
                    #pragma unroll
                    for (int rh = 0; rh < 2; rh++) {
                        const int s = m * 2 + rh;
                        float s0 = Da[rh * 2]     - ha0;
                        float s1 = Da[rh * 2 + 1] - ha1;
                        float s2 = Db[rh * 2]     - hb0;
                        float s3 = Db[rh * 2 + 1] - hb1;
                        if (s0 >= thr4[s]) {
                            int ix = atomicAdd(&scnt[srow[s]], 1);
                            if (ix < CAP) scand[srow[s] * CAP + ix] = (u16)k0a;
                        }
                        if (s1 >= thr4[s]) {
                            int ix = atomicAdd(&scnt[srow[s]], 1);
                            if (ix < CAP) scand[srow[s] * CAP + ix] = (u16)(k0a + 1);
                        }
                        if (s2 >= thr4[s]) {
                            int ix = atomicAdd(&scnt[srow[s]], 1);
                            if (ix < CAP) scand[srow[s] * CAP + ix] = (u16)k0b;
                        }
                        if (s3 >= thr4[s]) {
                            int ix = atomicAdd(&scnt[srow[s]], 1);
                            if (ix < CAP) scand[srow[s] * CAP + ix] = (u16)(k0b + 1);
                        }
                    }
                }
                cx0 = nx0; cx1 = nx1; cy0 = ny0; cy1 = ny1;
            }
        }
        // Warp-local sync suffices: scand/scnt for this warp's 32 rows are
        // written only by this warp's lanes.
        __syncwarp();

        // --- exact refine (lane l <-> row n). R2 bit chain + tie-break. ---
        float zv[64];
        #pragma unroll
        for (int c = 0; c < 64; c++) zv[c] = __ldg(zrow + c * 1024);

        const int cr = scnt[t];
        float best = 3.4e38f;
        int bi = 0;
        const int full = (cr > CAP);        // astronomically rare; still correct
        const int nev = full ? KCODES : cr;
        for (int i = 0; i < nev; i++) {
            const int k = full ? i : (int)scand[t * CAP + i];
            const float4* er = (const float4*)(E + k * 64);
            float c0 = 0.f, c1 = 0.f, c2 = 0.f, c3 = 0.f;
            #pragma unroll
            for (int j = 0; j < 16; j++) {
                float4 e4 = __ldg(er + j);
                c0 = fmaf(zv[4*j],     e4.x, c0);
                c1 = fmaf(zv[4*j + 1], e4.y, c1);
                c2 = fmaf(zv[4*j + 2], e4.z, c2);
                c3 = fmaf(zv[4*j + 3], e4.w, c3);
            }
            float s = __fadd_rn(__fadd_rn(c0, c2), __fadd_rn(c1, c3));
            float d = __fmaf_rn(-2.0f, s, __fadd_rn(zsq, sq[k]));
            if (d < best || (d == best && k < bi)) { best = d; bi = k; }
        }
        atomicAdd(&g_counts[bi], 1);

        // --- fused gather Zq + loss (bit-mimicking fl(z + fl(e - z))) ---
        float* zq = out + 1 + b * 65536 + p;
        const float4* er = (const float4*)(E + bi * 64);
        #pragma unroll
        for (int j = 0; j < 16; j++) {
            float4 e4 = __ldg(er + j);
            float ev[4] = {e4.x, e4.y, e4.z, e4.w};
            #pragma unroll
            for (int m = 0; m < 4; m++) {
                float z = zv[4*j + m];
                float diff = __fsub_rn(ev[m], z);
                ls = fmaf(diff, diff, ls);
                zq[(4*j + m) * 1024] = __fadd_rn(z, diff);
            }
        }
    }

    // --- loss reduction (inactive warps contribute 0) ---
    #pragma unroll
    for (int o = 16; o; o >>= 1) ls += __shfl_xor_sync(0xffffffffu, ls, o);
    __syncthreads();                 // emax reads long done; reuse smx
    if (l == 0) smx[w] = ls;
    __syncthreads();
    if (t == 0) {
        float s = 0.f;
        #pragma unroll
        for (int i = 0; i < 16; i++) s += smx[i];
        atomicAdd(&g_loss, (double)s);
        __threadfence();
        int old = atomicAdd(&g_done, 1);
        s_islast = (old == NCTA - 1);
    }
    __syncthreads();

    // --- last CTA: finalize (perplexity + scalars) ---
    if (s_islast) {
        __threadfence();
        float v = 0.f;
        #pragma unroll
        for (int i = 0; i < 2; i++) {
            int k = t + i * 512;
            float cnt = (float)g_counts[k];
            float pr = cnt * (1.0f / 65536.0f);
            v = fmaf(pr, log2f(pr + 1e-10f), v);
        }
        #pragma unroll
        for (int o = 16; o; o >>= 1) v += __shfl_xor_sync(0xffffffffu, v, o);
        if (l == 0) smx[w] = v;
        __syncthreads();
        if (t == 0) {
            float x = 0.f;
            #pragma unroll
            for (int i = 0; i < 16; i++) x += smx[i];
            float entropy = -x;
            float perp = exp2f(entropy);
            float lv = (float)(g_loss * (1.0 / 4194304.0));
            out[0] = lv + 0.25f * lv;
            out[1 + NROWS * DIM]     = lv;
            out[1 + NROWS * DIM + 1] = lv;
            out[1 + NROWS * DIM + 2] = perp;
            g_done = 0;              // reset for graph replay determinism
        }
    }
}

// ---------------------------------------------------------------------------
extern "C" void kernel_launch(void* const* d_in, const int* in_sizes, int n_in,
                              void* d_out, int out_size) {
    const float* in = (const float*)d_in[0];
    const float* E  = (const float*)d_in[1];
    float* out = (float*)d_out;

    cudaFuncSetAttribute(vq_main, cudaFuncAttributeMaxDynamicSharedMemorySize,
                         SMEM_SZ);
    prep_kernel<<<32, 32>>>(E);
    vq_main<<<NCTA, THREADS, SMEM_SZ>>>(in, E, out);
}